// round 5
// baseline (speedup 1.0000x reference)
#include <cuda_runtime.h>
#include <cuda_bf16.h>
#include <cstdint>

#define N_NODES 6144
#define HEADS 4
#define FH 64
#define FIN 512
#define NCLS 40
#define MAX_DEG 128

#define CONV_BLOCKS 96
#define CSR_BLOCKS 192

// ---------------- device scratch ----------------
__device__ int   g_col[N_NODES * MAX_DEG];
__device__ int   g_len[N_NODES];
__device__ float g_Wh[HEADS * N_NODES * FH];
__device__ float g_f1[HEADS * N_NODES];
__device__ float g_f2[HEADS * N_NODES];
__device__ float g_hcat[N_NODES * HEADS * FH];
__device__ float g_Who[N_NODES * NCLS];
__device__ float g_f1o[N_NODES];
__device__ float g_f2o[N_NODES];
// split-bf16 operands
__device__ __nv_bfloat16 g_xhi[N_NODES * FIN];
__device__ __nv_bfloat16 g_xlo[N_NODES * FIN];
__device__ __nv_bfloat16 g_Whi[HEADS * FH * FIN];   // transposed: [n=head*64+fh][k]
__device__ __nv_bfloat16 g_Wlo[HEADS * FH * FIN];

// ---------------- helpers ----------------
__device__ __forceinline__ float warpMax(float v) {
#pragma unroll
    for (int o = 16; o; o >>= 1) v = fmaxf(v, __shfl_xor_sync(0xffffffffu, v, o));
    return v;
}
__device__ __forceinline__ float warpSum(float v) {
#pragma unroll
    for (int o = 16; o; o >>= 1) v += __shfl_xor_sync(0xffffffffu, v, o);
    return v;
}
__device__ __forceinline__ float lrelu(float x) { return x > 0.f ? x : 0.2f * x; }
__device__ __forceinline__ float elu(float x) { return x > 0.f ? x : (expf(x) - 1.f); }

__device__ __forceinline__ void ldsm_x4(uint32_t* r, uint32_t addr) {
    asm volatile("ldmatrix.sync.aligned.m8n8.x4.shared.b16 {%0,%1,%2,%3}, [%4];"
        : "=r"(r[0]), "=r"(r[1]), "=r"(r[2]), "=r"(r[3]) : "r"(addr));
}
__device__ __forceinline__ void mma16816(float* d, const uint32_t* a, const uint32_t* b) {
    asm volatile("mma.sync.aligned.m16n8k16.row.col.f32.bf16.bf16.f32 "
        "{%0,%1,%2,%3}, {%4,%5,%6,%7}, {%8,%9}, {%0,%1,%2,%3};"
        : "+f"(d[0]), "+f"(d[1]), "+f"(d[2]), "+f"(d[3])
        : "r"(a[0]), "r"(a[1]), "r"(a[2]), "r"(a[3]), "r"(b[0]), "r"(b[1]));
}

// ============ K0: bf16-split conversion + adjacency compaction ============
__global__ __launch_bounds__(256) void prep_kernel(
    const float* __restrict__ x, const float* __restrict__ W,
    const float* __restrict__ adj) {
    int b = blockIdx.x;
    if (b < CONV_BLOCKS) {
        int tid = b * 256 + threadIdx.x;
        int stride = CONV_BLOCKS * 256;
        const float4* x4 = reinterpret_cast<const float4*>(x);
        for (int i = tid; i < N_NODES * FIN / 4; i += stride) {
            float4 v = x4[i];
            float vv[4] = {v.x, v.y, v.z, v.w};
#pragma unroll
            for (int u = 0; u < 4; u++) {
                __nv_bfloat16 h = __float2bfloat16(vv[u]);
                g_xhi[i * 4 + u] = h;
                g_xlo[i * 4 + u] = __float2bfloat16(vv[u] - __bfloat162float(h));
            }
        }
        // W transpose + split: Wt[n][k] = W[head][k][fh],  n = head*64+fh
        for (int i = tid; i < HEADS * FH * FIN; i += stride) {
            int n = i >> 9;            // /FIN
            int k = i & (FIN - 1);
            int head = n >> 6, fh = n & 63;
            float v = W[((size_t)head * FIN + k) * FH + fh];
            __nv_bfloat16 hh = __float2bfloat16(v);
            g_Whi[i] = hh;
            g_Wlo[i] = __float2bfloat16(v - __bfloat162float(hh));
        }
    } else {
        int warp = threadIdx.x >> 5, lane = threadIdx.x & 31;
        int wid = (b - CONV_BLOCKS) * 8 + warp;
        unsigned lt = (1u << lane) - 1u;
        for (int rr = 0; rr < 4; rr++) {
            int row = wid * 4 + rr;
            const float4* rp = reinterpret_cast<const float4*>(adj + (size_t)row * N_NODES);
            int* outp = g_col + (size_t)row * MAX_DEG;
            int count = 0;
            for (int it = 0; it < N_NODES / 128; it += 4) {
                float4 v[4];
#pragma unroll
                for (int u = 0; u < 4; u++) v[u] = rp[(it + u) * 32 + lane];
#pragma unroll
                for (int u = 0; u < 4; u++) {
                    float4 vv = v[u];
                    int c0 = vv.x > 0.f, c1 = vv.y > 0.f, c2 = vv.z > 0.f, c3 = vv.w > 0.f;
                    unsigned m0b = __ballot_sync(0xffffffffu, c0);
                    unsigned m1b = __ballot_sync(0xffffffffu, c1);
                    unsigned m2b = __ballot_sync(0xffffffffu, c2);
                    unsigned m3b = __ballot_sync(0xffffffffu, c3);
                    int before = __popc(m0b & lt) + __popc(m1b & lt) + __popc(m2b & lt) + __popc(m3b & lt);
                    int pos = count + before;
                    int col0 = ((it + u) * 32 + lane) * 4;
                    if (c0) { if (pos < MAX_DEG) outp[pos] = col0;     pos++; }
                    if (c1) { if (pos < MAX_DEG) outp[pos] = col0 + 1; pos++; }
                    if (c2) { if (pos < MAX_DEG) outp[pos] = col0 + 2; pos++; }
                    if (c3) { if (pos < MAX_DEG) outp[pos] = col0 + 3; pos++; }
                    count += __popc(m0b) + __popc(m1b) + __popc(m2b) + __popc(m3b);
                }
            }
            if (lane == 0) g_len[row] = count < MAX_DEG ? count : MAX_DEG;
        }
    }
}

// ============ K1: HMMA split-bf16 GEMM: Wh = x @ Wall  (6144x512 @ 512x256) ============
// grid 96 = 48 m-tiles x 2 n-halves. block 256 thr = 8 warps (4m x 2n), warp tile 32x64.
// smem rows padded to 80B (16B-aligned, conflict-free ldmatrix).
#define SROW 80
#define NCHUNK 48   // 3 segments x 16 k-chunks of 32

__global__ __launch_bounds__(256) void gemm_mma_kernel() {
    __shared__ __align__(16) char sA[2][128 * SROW];
    __shared__ __align__(16) char sB[2][128 * SROW];
    int tid = threadIdx.x;
    int lane = tid & 31, wid = tid >> 5;
    int wm = wid & 3, wn = wid >> 2;
    int m0 = (blockIdx.x >> 1) * 128;
    int nh = blockIdx.x & 1;

    const __nv_bfloat16* Alist[3] = {g_xhi, g_xlo, g_xhi};
    const __nv_bfloat16* Blist[3] = {g_Whi, g_Whi, g_Wlo};

    int crow = tid >> 1;
    int cc0 = (tid & 1) * 2;

    float acc[2][8][4];
#pragma unroll
    for (int i = 0; i < 2; i++)
#pragma unroll
        for (int j = 0; j < 8; j++)
#pragma unroll
            for (int q = 0; q < 4; q++) acc[i][j][q] = 0.f;

    // ldmatrix address components (constant per thread)
    int g = lane >> 3;
    int arow_lo = (lane & 7) + (g & 1) * 8;     // A: row within 16, chunk sel = g>>1
    int ach_sel = g >> 1;
    int brow_add = (g >> 1) * 8;                // B: n add, chunk sel = g&1
    int bch_sel = g & 1;

    uint32_t sAb[2], sBb[2];
    sAb[0] = (uint32_t)__cvta_generic_to_shared(sA[0]);
    sAb[1] = (uint32_t)__cvta_generic_to_shared(sA[1]);
    sBb[0] = (uint32_t)__cvta_generic_to_shared(sB[0]);
    sBb[1] = (uint32_t)__cvta_generic_to_shared(sB[1]);

    // prologue: load chunk 0
    uint4 pr[4];
    {
        const __nv_bfloat16* As = Alist[0];
        const __nv_bfloat16* Bs = Blist[0];
        const uint4* ap = reinterpret_cast<const uint4*>(As + (size_t)(m0 + crow) * FIN + cc0 * 8);
        const uint4* bp = reinterpret_cast<const uint4*>(Bs + (size_t)(nh * 128 + crow) * FIN + cc0 * 8);
        pr[0] = ap[0]; pr[1] = ap[1]; pr[2] = bp[0]; pr[3] = bp[1];
        *reinterpret_cast<uint4*>(sA[0] + crow * SROW + cc0 * 16) = pr[0];
        *reinterpret_cast<uint4*>(sA[0] + crow * SROW + (cc0 + 1) * 16) = pr[1];
        *reinterpret_cast<uint4*>(sB[0] + crow * SROW + cc0 * 16) = pr[2];
        *reinterpret_cast<uint4*>(sB[0] + crow * SROW + (cc0 + 1) * 16) = pr[3];
    }
    __syncthreads();

    for (int it = 0; it < NCHUNK; it++) {
        int buf = it & 1;
        bool more = (it + 1 < NCHUNK);
        if (more) {
            int nit = it + 1;
            int seg = nit >> 4;
            int k0 = (nit & 15) * 32;
            const __nv_bfloat16* As = Alist[seg];
            const __nv_bfloat16* Bs = Blist[seg];
            const uint4* ap = reinterpret_cast<const uint4*>(As + (size_t)(m0 + crow) * FIN + k0 + cc0 * 8);
            const uint4* bp = reinterpret_cast<const uint4*>(Bs + (size_t)(nh * 128 + crow) * FIN + k0 + cc0 * 8);
            pr[0] = ap[0]; pr[1] = ap[1]; pr[2] = bp[0]; pr[3] = bp[1];
        }
        // compute on buf
#pragma unroll
        for (int kt = 0; kt < 2; kt++) {
            uint32_t afr[2][4];
#pragma unroll
            for (int mi = 0; mi < 2; mi++) {
                int row = wm * 32 + mi * 16 + arow_lo;
                int ch = kt * 2 + ach_sel;
                ldsm_x4(afr[mi], sAb[buf] + row * SROW + ch * 16);
            }
            uint32_t bfr[4][4];
#pragma unroll
            for (int ni4 = 0; ni4 < 4; ni4++) {
                int nrow = wn * 64 + ni4 * 16 + (lane & 7) + brow_add;
                int ch = kt * 2 + bch_sel;
                ldsm_x4(bfr[ni4], sBb[buf] + nrow * SROW + ch * 16);
            }
#pragma unroll
            for (int mi = 0; mi < 2; mi++)
#pragma unroll
                for (int ni4 = 0; ni4 < 4; ni4++) {
                    mma16816(acc[mi][ni4 * 2], afr[mi], &bfr[ni4][0]);
                    mma16816(acc[mi][ni4 * 2 + 1], afr[mi], &bfr[ni4][2]);
                }
        }
        if (more) {
            int nb = buf ^ 1;
            *reinterpret_cast<uint4*>(sA[nb] + crow * SROW + cc0 * 16) = pr[0];
            *reinterpret_cast<uint4*>(sA[nb] + crow * SROW + (cc0 + 1) * 16) = pr[1];
            *reinterpret_cast<uint4*>(sB[nb] + crow * SROW + cc0 * 16) = pr[2];
            *reinterpret_cast<uint4*>(sB[nb] + crow * SROW + (cc0 + 1) * 16) = pr[3];
        }
        __syncthreads();
    }

    // epilogue: write Wh in [head][node][fh] layout
#pragma unroll
    for (int mi = 0; mi < 2; mi++) {
#pragma unroll
        for (int ni = 0; ni < 8; ni++) {
            int row = m0 + wm * 32 + mi * 16 + (lane >> 2);
            int col = nh * 128 + wn * 64 + ni * 8 + (lane & 3) * 2;
            int head = col >> 6, fh = col & 63;
            float* base = g_Wh + ((size_t)head * N_NODES) * FH + fh;
            *reinterpret_cast<float2*>(base + (size_t)row * FH) =
                make_float2(acc[mi][ni][0], acc[mi][ni][1]);
            *reinterpret_cast<float2*>(base + (size_t)(row + 8) * FH) =
                make_float2(acc[mi][ni][2], acc[mi][ni][3]);
        }
    }
}

// ============ K2: f1/f2 per (head,node): warp per row ============
__global__ void compute_f_kernel(const float* __restrict__ a1, const float* __restrict__ a2) {
    int gw = (blockIdx.x * blockDim.x + threadIdx.x) >> 5;
    int lane = threadIdx.x & 31;
    if (gw >= HEADS * N_NODES) return;
    int h = gw / N_NODES;
    const float* r = g_Wh + (size_t)gw * FH;
    float w0 = r[lane], w1 = r[lane + 32];
    float v1 = w0 * a1[h * FH + lane] + w1 * a1[h * FH + lane + 32];
    float v2 = w0 * a2[h * FH + lane] + w1 * a2[h * FH + lane + 32];
    v1 = warpSum(v1);
    v2 = warpSum(v2);
    if (lane == 0) { g_f1[gw] = v1; g_f2[gw] = v2; }
}

// ============ K3: sparse attention per head + ELU + concat ============
__global__ __launch_bounds__(256) void attn_heads_kernel() {
    __shared__ float sw[8][MAX_DEG];
    __shared__ int   sc[8][MAX_DEG];
    int warp = threadIdx.x >> 5, lane = threadIdx.x & 31;
    int h = blockIdx.y;
    int i = blockIdx.x * 8 + warp;
    int len = g_len[i];
    const int* cols = g_col + (size_t)i * MAX_DEG;
    float f1i = g_f1[h * N_NODES + i];
    const float* f2h = g_f2 + (size_t)h * N_NODES;

    float m = -1e30f;
    for (int t = lane; t < len; t += 32) {
        int j = __ldg(cols + t);
        sc[warp][t] = j;
        float e = lrelu(f1i + f2h[j]);
        sw[warp][t] = e;
        m = fmaxf(m, e);
    }
    m = warpMax(m);
    float s = 0.f;
    for (int t = lane; t < len; t += 32) {
        float we = expf(sw[warp][t] - m);
        sw[warp][t] = we;
        s += we;
    }
    s = warpSum(s);
    float inv = 1.f / s;
    __syncwarp();

    const float* WhH = g_Wh + (size_t)h * N_NODES * FH;
    float accA[4] = {0.f, 0.f, 0.f, 0.f}, accB[4] = {0.f, 0.f, 0.f, 0.f};
    int t = 0;
    for (; t + 4 <= len; t += 4) {
#pragma unroll
        for (int u = 0; u < 4; u++) {
            int j = sc[warp][t + u];
            float wgt = sw[warp][t + u];
            const float* wr = WhH + (size_t)j * FH;
            accA[u] += wgt * wr[lane];
            accB[u] += wgt * wr[lane + 32];
        }
    }
    for (; t < len; t++) {
        int j = sc[warp][t];
        float wgt = sw[warp][t];
        const float* wr = WhH + (size_t)j * FH;
        accA[0] += wgt * wr[lane];
        accB[0] += wgt * wr[lane + 32];
    }
    float r0 = elu((accA[0] + accA[1] + accA[2] + accA[3]) * inv);
    float r1 = elu((accB[0] + accB[1] + accB[2] + accB[3]) * inv);
    g_hcat[(size_t)i * (HEADS * FH) + h * FH + lane] = r0;
    g_hcat[(size_t)i * (HEADS * FH) + h * FH + 32 + lane] = r1;
}

// ============ K4: Who = hcat @ Wo, fused f1o/f2o ============
__global__ __launch_bounds__(256) void out_proj_kernel(
    const float* __restrict__ Wo, const float* __restrict__ ao1,
    const float* __restrict__ ao2) {
    __shared__ float sWo[(HEADS * FH) * NCLS];
    for (int t = threadIdx.x; t < (HEADS * FH) * NCLS; t += blockDim.x) sWo[t] = Wo[t];
    __syncthreads();
    int warp = threadIdx.x >> 5, lane = threadIdx.x & 31;
    int i = blockIdx.x * 8 + warp;
    const float* hr = g_hcat + (size_t)i * (HEADS * FH);
    bool hi = lane < (NCLS - 32);
    float acc0 = 0.f, acc1 = 0.f;
    for (int k0 = 0; k0 < HEADS * FH; k0 += 32) {
        float hv = hr[k0 + lane];
#pragma unroll
        for (int kk = 0; kk < 32; kk++) {
            float hb = __shfl_sync(0xffffffffu, hv, kk);
            const float* wrow = sWo + (k0 + kk) * NCLS;
            acc0 += hb * wrow[lane];
            if (hi) acc1 += hb * wrow[32 + lane];
        }
    }
    g_Who[(size_t)i * NCLS + lane] = acc0;
    if (hi) g_Who[(size_t)i * NCLS + 32 + lane] = acc1;
    float v1 = acc0 * ao1[lane] + (hi ? acc1 * ao1[32 + lane] : 0.f);
    float v2 = acc0 * ao2[lane] + (hi ? acc1 * ao2[32 + lane] : 0.f);
    v1 = warpSum(v1);
    v2 = warpSum(v2);
    if (lane == 0) { g_f1o[i] = v1; g_f2o[i] = v2; }
}

// ============ K5: output sparse attention + ELU + log_softmax ============
__global__ __launch_bounds__(256) void attn_out_kernel(float* __restrict__ out) {
    __shared__ float sw[8][MAX_DEG];
    __shared__ int   sc[8][MAX_DEG];
    int warp = threadIdx.x >> 5, lane = threadIdx.x & 31;
    int i = blockIdx.x * 8 + warp;
    int len = g_len[i];
    const int* cols = g_col + (size_t)i * MAX_DEG;
    float f1i = g_f1o[i];

    float m = -1e30f;
    for (int t = lane; t < len; t += 32) {
        int j = __ldg(cols + t);
        sc[warp][t] = j;
        float e = lrelu(f1i + g_f2o[j]);
        sw[warp][t] = e;
        m = fmaxf(m, e);
    }
    m = warpMax(m);
    float s = 0.f;
    for (int t = lane; t < len; t += 32) {
        float we = expf(sw[warp][t] - m);
        sw[warp][t] = we;
        s += we;
    }
    s = warpSum(s);
    float inv = 1.f / s;
    __syncwarp();

    bool hi = lane < (NCLS - 32);
    float accA[4] = {0.f, 0.f, 0.f, 0.f};
    float accB[2] = {0.f, 0.f};
    int t = 0;
    for (; t + 4 <= len; t += 4) {
#pragma unroll
        for (int u = 0; u < 4; u++) {
            int j = sc[warp][t + u];
            float wgt = sw[warp][t + u];
            const float* wr = g_Who + (size_t)j * NCLS;
            accA[u] += wgt * wr[lane];
            if (hi) accB[u & 1] += wgt * wr[32 + lane];
        }
    }
    for (; t < len; t++) {
        int j = sc[warp][t];
        float wgt = sw[warp][t];
        const float* wr = g_Who + (size_t)j * NCLS;
        accA[0] += wgt * wr[lane];
        if (hi) accB[0] += wgt * wr[32 + lane];
    }
    float v0 = elu((accA[0] + accA[1] + accA[2] + accA[3]) * inv);
    float v1 = hi ? elu((accB[0] + accB[1]) * inv) : -1e30f;
    float mm = warpMax(fmaxf(v0, v1));
    float se = expf(v0 - mm) + (hi ? expf(v1 - mm) : 0.f);
    se = warpSum(se);
    float lse = logf(se);
    out[(size_t)i * NCLS + lane] = v0 - mm - lse;
    if (hi) out[(size_t)i * NCLS + 32 + lane] = v1 - mm - lse;
}

// ---------------- launch ----------------
extern "C" void kernel_launch(void* const* d_in, const int* in_sizes, int n_in,
                              void* d_out, int out_size) {
    const float* x   = (const float*)d_in[0];
    const float* adj = (const float*)d_in[1];
    const float* W   = (const float*)d_in[2];
    const float* a1  = (const float*)d_in[3];
    const float* a2  = (const float*)d_in[4];
    const float* Wo  = (const float*)d_in[5];
    const float* ao1 = (const float*)d_in[6];
    const float* ao2 = (const float*)d_in[7];
    float* out = (float*)d_out;
    (void)in_sizes; (void)n_in; (void)out_size;

    prep_kernel<<<CONV_BLOCKS + CSR_BLOCKS, 256>>>(x, W, adj);
    gemm_mma_kernel<<<96, 256>>>();
    compute_f_kernel<<<HEADS * N_NODES / 8, 256>>>(a1, a2);
    attn_heads_kernel<<<dim3(N_NODES / 8, HEADS), 256>>>();
    out_proj_kernel<<<N_NODES / 8, 256>>>(Wo, ao1, ao2);
    attn_out_kernel<<<N_NODES / 8, 256>>>(out);
}